// round 14
// baseline (speedup 1.0000x reference)
#include <cuda_runtime.h>
#include <cuda_bf16.h>

// CenterLoss: loss = LAMBDA_C * mean_b sum_d (features[b,d] - centers[labels[b],d])^2
// B=65536, D=256, C=100000.
//
// R12: single kernel via PACKED ATOMIC. Workers are byte-identical to R11
// (best two-kernel: 16.86us) except the per-block atomicAdd operand also
// carries a completion count in the high 16 bits:
//     add (1<<48) | (partial * 2^21)
// The returned old value tells the leader atomically if it is the LAST block
// (old>>48 == NBLOCKS-1) AND gives it the full sum (old_low + its own part).
// No fence, no watcher, no second atomic, no separate partial stores — the
// failure modes of fusion attempts R3/R5/R6 are all absent. Last block writes
// out[0] and plain-stores g_acc=0 (all contributions provably included).
// Integer accumulation is order-invariant => bitwise-deterministic.

#define BATCH     65536
#define FEAT_DIM  256
#define LAMBDA_C  1.0

#define WARPS_PER_BLOCK 8
#define ROWS_PER_WARP   2
#define ROWS_PER_BLOCK  (WARPS_PER_BLOCK * ROWS_PER_WARP)      // 16
#define NBLOCKS         (BATCH / ROWS_PER_BLOCK)               // 4096 ≈ 3.5 waves

// Low 48 bits: fixed-point sum, scale 2^21. Max total ~3.4e7*2^21 ≈ 7.1e13 < 2^48.
// High 16 bits: block completion count (4096 < 2^16).
#define FP_SCALE   2097152.0f        /* 2^21 */
#define COUNT_ONE  (1ull << 48)
#define SUM_MASK   (COUNT_ONE - 1ull)

__device__ unsigned long long g_acc;   // zero-init; reset by last block each replay

__global__ __launch_bounds__(256, 8)
void center_loss_kernel(const float* __restrict__ features,
                        const int*   __restrict__ labels,
                        const float* __restrict__ centers,
                        float*       __restrict__ out) {
    const int warp = threadIdx.x >> 5;
    const int lane = threadIdx.x & 31;
    const int row0 = blockIdx.x * ROWS_PER_BLOCK + warp * ROWS_PER_WARP;

    float acc = 0.0f;

    #pragma unroll
    for (int r = 0; r < ROWS_PER_WARP; r++) {
        const int row = row0 + r;
        const float4* frow = reinterpret_cast<const float4*>(features + (size_t)row * FEAT_DIM);
        const int lab = __ldg(&labels[row]);
        const float4* crow = reinterpret_cast<const float4*>(centers + (size_t)lab * FEAT_DIM);

        // 64 float4 per row / 32 lanes = 2 per lane; 4 loads issued up front.
        float4 a0 = __ldg(&frow[lane]);         // features: normal policy, L2-resident across replays
        float4 a1 = __ldg(&frow[lane + 32]);
        float4 b0 = __ldcs(&crow[lane]);        // centers: evict-first DRAM stream
        float4 b1 = __ldcs(&crow[lane + 32]);

        float d;
        d = a0.x - b0.x; acc = fmaf(d, d, acc);
        d = a0.y - b0.y; acc = fmaf(d, d, acc);
        d = a0.z - b0.z; acc = fmaf(d, d, acc);
        d = a0.w - b0.w; acc = fmaf(d, d, acc);
        d = a1.x - b1.x; acc = fmaf(d, d, acc);
        d = a1.y - b1.y; acc = fmaf(d, d, acc);
        d = a1.z - b1.z; acc = fmaf(d, d, acc);
        d = a1.w - b1.w; acc = fmaf(d, d, acc);
    }

    // warp reduce (float)
    #pragma unroll
    for (int off = 16; off > 0; off >>= 1)
        acc += __shfl_xor_sync(0xffffffffu, acc, off);

    __shared__ float s[WARPS_PER_BLOCK];
    if (lane == 0) s[warp] = acc;
    __syncthreads();

    if (threadIdx.x == 0) {
        float t = 0.0f;
        #pragma unroll
        for (int i = 0; i < WARPS_PER_BLOCK; i++) t += s[i];

        // Single packed atomic: sum contribution + completion tick in one op.
        const unsigned long long mine = (unsigned long long)llrintf(t * FP_SCALE);
        const unsigned long long old  = atomicAdd(&g_acc, COUNT_ONE | mine);

        if ((old >> 48) == (unsigned long long)(NBLOCKS - 1)) {
            // Last block: old already contains every other block's sum.
            const unsigned long long total = (old & SUM_MASK) + mine;
            out[0] = (float)(LAMBDA_C * ((double)total / (double)FP_SCALE / (double)BATCH));
            g_acc = 0ull;   // all contributions included (count proves it); safe plain store
        }
    }
}

extern "C" void kernel_launch(void* const* d_in, const int* in_sizes, int n_in,
                              void* d_out, int out_size) {
    const float* features = (const float*)d_in[0];
    const int*   labels   = (const int*)d_in[1];
    const float* centers  = (const float*)d_in[2];
    float* out = (float*)d_out;

    center_loss_kernel<<<NBLOCKS, 256>>>(features, labels, centers, out);
}